// round 11
// baseline (speedup 1.0000x reference)
#include <cuda_runtime.h>
#include <cstdint>
#include <cstddef>

#define SEQ    512
#define BATCH  64
#define INDIM  128
#define HDIM   512

#define GROWS  4            // rows per group (2 groups per cluster = 8 rows)
#define RT     256

typedef unsigned long long u64;

__device__ __forceinline__ u64 fma2(u64 a, u64 b, u64 c) {
    u64 d;
    asm("fma.rn.f32x2 %0, %1, %2, %3;" : "=l"(d) : "l"(a), "l"(b), "l"(c));
    return d;
}
__device__ __forceinline__ uint32_t smem_u32(const void* p) {
    uint32_t a;
    asm("{ .reg .u64 t; cvta.to.shared.u64 t, %1; cvt.u32.u64 %0, t; }" : "=r"(a) : "l"(p));
    return a;
}
__device__ __forceinline__ uint32_t mapa_u32(uint32_t a, uint32_t r) {
    uint32_t d;
    asm("mapa.shared::cluster.u32 %0, %1, %2;" : "=r"(d) : "r"(a), "r"(r));
    return d;
}
__device__ __forceinline__ void mbar_init(uint32_t a, uint32_t cnt) {
    asm volatile("mbarrier.init.shared.b64 [%0], %1;" :: "r"(a), "r"(cnt) : "memory");
}
__device__ __forceinline__ void mbar_wait_cluster(uint32_t a, uint32_t parity) {
    asm volatile(
        "{\n\t"
        ".reg .pred P;\n\t"
        "WL_%=:\n\t"
        "mbarrier.try_wait.parity.acquire.cluster.shared::cta.b64 P, [%0], %1, 0x989680;\n\t"
        "@P bra.uni WD_%=;\n\t"
        "bra.uni WL_%=;\n\t"
        "WD_%=:\n\t"
        "}"
        :: "r"(a), "r"(parity) : "memory");
}
__device__ __forceinline__ void mbar_arrive_remote(uint32_t a) {
    asm volatile("mbarrier.arrive.release.cluster.shared::cluster.b64 _, [%0];"
                 :: "r"(a) : "memory");
}
__device__ __forceinline__ void fence_cluster() {
    asm volatile("fence.acq_rel.cluster;" ::: "memory");
}
__device__ __forceinline__ void st_cluster_b64(uint32_t a, u64 v) {
    asm volatile("st.shared::cluster.b64 [%0], %1;" :: "r"(a), "l"(v) : "memory");
}
#define CLUSTER_SYNC() do { \
    asm volatile("barrier.cluster.arrive.aligned;" ::: "memory"); \
    asm volatile("barrier.cluster.wait.aligned;"   ::: "memory"); \
} while (0)

// ---------------------------------------------------------------------------
// xi kernel (validated R3-R10): out[s][b][h] = x.Wi + bi + bh
// ---------------------------------------------------------------------------
__global__ __launch_bounds__(256) void xi_kernel(
    const float* __restrict__ x, const float* __restrict__ Wi,
    const float* __restrict__ bi, const float* __restrict__ bh,
    float* __restrict__ out)
{
    extern __shared__ float sm[];
    float* ws = sm;               // [128][130]
    float* xs = sm + 128 * 130;   // [64][130]

    const int tid = threadIdx.x;
    const int sb0 = blockIdx.x * 64;
    const int h0  = blockIdx.y * 128;

    for (int i = tid; i < 128 * INDIM; i += 256) {
        int r = i >> 7, k = i & 127;
        ws[r * 130 + k] = Wi[(h0 + r) * INDIM + k];
    }
    for (int i = tid; i < 64 * INDIM; i += 256) {
        int r = i >> 7, k = i & 127;
        xs[r * 130 + k] = x[(size_t)(sb0 + r) * INDIM + k];
    }
    __syncthreads();

    const int w  = tid >> 5;
    const int tx = tid & 31;

    u64 acc2[8][4];
#pragma unroll
    for (int i = 0; i < 8; i++)
#pragma unroll
        for (int j = 0; j < 4; j++) acc2[i][j] = 0ull;

    const u64* xb2 = (const u64*)xs + (w * 8) * 65;
    const u64* wb2 = (const u64*)ws;

#pragma unroll 4
    for (int kp = 0; kp < 64; kp++) {
        u64 xv[8], wv[4];
#pragma unroll
        for (int i = 0; i < 8; i++) xv[i] = xb2[i * 65 + kp];
#pragma unroll
        for (int j = 0; j < 4; j++) wv[j] = wb2[(j * 32 + tx) * 65 + kp];
#pragma unroll
        for (int i = 0; i < 8; i++)
#pragma unroll
            for (int j = 0; j < 4; j++) acc2[i][j] = fma2(xv[i], wv[j], acc2[i][j]);
    }

#pragma unroll
    for (int j = 0; j < 4; j++) {
        int h = h0 + j * 32 + tx;
        float b = bi[h] + bh[h];
#pragma unroll
        for (int i = 0; i < 8; i++) {
            float2 a = *reinterpret_cast<float2*>(&acc2[i][j]);
            out[(size_t)(sb0 + w * 8 + i) * HDIM + h] = a.x + a.y + b;
        }
    }
}

// ---------------------------------------------------------------------------
// Recurrence, templated on cluster size CLV (16 preferred, 8 fallback).
// 8 clusters x CLV CTAs; CTA owns JC=512/CLV j-cols (Wh tile in SMEM).
// Two groups of 4 rows interleaved (A/B) hide the DSMEM round trip.
// Warp tile 4b x JT j, lane = k-pair slice (32-way), u64 f32x2 accumulators,
// butterfly reduce; even-output lanes push packed b64 pairs to CLV-1 peers;
// __syncthreads; tid<CLV fence + one remote release-arrive each.
// ---------------------------------------------------------------------------
template<int CLV>
__global__ __launch_bounds__(RT, 1)
void rnn_kernel(const float* __restrict__ Wh, float* __restrict__ out)
{
    constexpr int JC = HDIM / CLV;   // j columns per CTA (32 or 64)
    constexpr int JT = JC / 8;       // j per warp (4 or 8)
    constexpr int NO = 4 * JT;       // outputs per warp (16 or 32)

    extern __shared__ float sm[];
    float* sWh = sm;                          // [JC][512]
    float* hbA = sm + JC * HDIM;              // [2][4][512]
    float* hbB = hbA + 2 * GROWS * HDIM;      // [2][4][512]
    u64*   mbar = (u64*)(hbB + 2 * GROWS * HDIM);  // A0,A1,B0,B1

    const int tid = threadIdx.x;
    uint32_t rank;
    asm("mov.u32 %0, %%cluster_ctarank;" : "=r"(rank));
    const int gbase = (blockIdx.x / CLV) * 8;

    const uint32_t mb_base = smem_u32(mbar);
    if (tid == 0) {
#pragma unroll
        for (int i = 0; i < 4; i++) mbar_init(mb_base + i * 8, CLV);
    }
    {   // load Wh rows [rank*JC, +JC) once
        const float4* src = (const float4*)(Wh + (size_t)rank * JC * HDIM);
        float4* dst = (float4*)sWh;
        for (int i = tid; i < JC * HDIM / 4; i += RT) dst[i] = src[i];
    }
    __syncthreads();
    CLUSTER_SYNC();

    const int w    = tid >> 5;
    const int lane = tid & 31;
    const int o    = lane & (NO - 1);   // this lane's output after butterfly
    const int b    = o / JT;            // row in group
    const int jj   = o % JT;
    const int ojl  = rank * JC + w * JT + jj;
    const int obA  = gbase + b;
    const int obB  = gbase + 4 + b;

    const ulonglong2* wv2 = (const ulonglong2*)sWh + (w * JT) * (HDIM / 4) + lane;

    const uint32_t hbA_base = smem_u32(hbA);
    uint32_t peer_hbA[CLV];
#pragma unroll
    for (int r = 0; r < CLV; r++)
        peer_hbA[r] = mapa_u32(hbA_base, (rank + r) & (CLV - 1));
    const uint32_t HB_DELTA = 2 * GROWS * HDIM * 4;
    const uint32_t my_peer_mb = (tid < CLV)
        ? mapa_u32(mb_base, (rank + tid) & (CLV - 1)) : 0u;

    int phA[2] = {0, 0}, phB[2] = {0, 0};

    const size_t obaseA = (size_t)obA * HDIM + ojl;
    const size_t obaseB = (size_t)obB * HDIM + ojl;
    float xiA = __ldg(out + obaseA);
    float xiB = __ldg(out + obaseB);

    for (int t = 1; t <= SEQ; t++) {
        const int bcur  = t & 1;
        const int bprev = 1 - bcur;
        const size_t step_off = (size_t)(t - 1) * (BATCH * HDIM);

#pragma unroll
        for (int G = 0; G < 2; G++) {
            float* hbG = G ? hbB : hbA;
            const uint32_t mboff = G * 16;
            int* phG = G ? phB : phA;
            const float xiv = G ? xiB : xiA;
            const size_t obase = G ? obaseB : obaseA;

            float sum = 0.f;
            if (t > 1) {
                mbar_wait_cluster(mb_base + mboff + bprev * 8, phG[bprev]);
                phG[bprev] ^= 1;
                const ulonglong2* hp =
                    (const ulonglong2*)(hbG + bprev * GROWS * HDIM) + lane;

                u64 acc[4][JT];
#pragma unroll
                for (int i = 0; i < 4; i++)
#pragma unroll
                    for (int j = 0; j < JT; j++) acc[i][j] = 0ull;
#pragma unroll
                for (int d = 0; d < 4; d++) {    // k = d*128 + lane*4
                    ulonglong2 hv[4], wv[JT];
#pragma unroll
                    for (int i = 0; i < 4; i++) hv[i] = hp[i * (HDIM / 4) + d * 32];
#pragma unroll
                    for (int j = 0; j < JT; j++) wv[j] = wv2[j * (HDIM / 4) + d * 32];
#pragma unroll
                    for (int i = 0; i < 4; i++)
#pragma unroll
                        for (int j = 0; j < JT; j++) {
                            acc[i][j] = fma2(hv[i].x, wv[j].x, acc[i][j]);
                            acc[i][j] = fma2(hv[i].y, wv[j].y, acc[i][j]);
                        }
                }
                float v[NO];
#pragma unroll
                for (int i = 0; i < 4; i++)
#pragma unroll
                    for (int j = 0; j < JT; j++) {
                        float2 a = *reinterpret_cast<float2*>(&acc[i][j]);
                        v[i * JT + j] = a.x + a.y;
                    }
                if constexpr (NO == 32) {
#pragma unroll
                    for (int m = 0; m < 5; m++) {
                        const int mb2 = (lane >> m) & 1;
#pragma unroll
                        for (int j2 = 0; j2 < (16 >> m); j2++) {
                            float send = v[2 * j2 + 1 - mb2];
                            float recv = __shfl_xor_sync(0xffffffffu, send, 1 << m);
                            v[j2] = v[2 * j2 + mb2] + recv;
                        }
                    }
                } else {  // NO == 16: 4 output-split stages + final slice fold
#pragma unroll
                    for (int m = 0; m < 4; m++) {
                        const int mb2 = (lane >> m) & 1;
#pragma unroll
                        for (int j2 = 0; j2 < (8 >> m); j2++) {
                            float send = v[2 * j2 + 1 - mb2];
                            float recv = __shfl_xor_sync(0xffffffffu, send, 1 << m);
                            v[j2] = v[2 * j2 + mb2] + recv;
                        }
                    }
                    v[0] += __shfl_xor_sync(0xffffffffu, v[0], 16);
                }
                sum = v[0];
            }

            const float hval = tanhf(sum + xiv);
            if (t < SEQ) {
                float nv = __ldg(out + step_off + BATCH * HDIM + obase);
                if (G) xiB = nv; else xiA = nv;
            }

            if (t < SEQ) {
                float nxt = __shfl_down_sync(0xffffffffu, hval, 1);
                if (lane < NO && !(o & 1)) {   // even output lanes push (jj, jj+1)
                    float2 p2 = make_float2(hval, nxt);
                    u64 pv = *reinterpret_cast<u64*>(&p2);
                    const uint32_t boff = bcur * GROWS * HDIM + b * HDIM + ojl;
                    *reinterpret_cast<u64*>(hbG + boff) = pv;   // self, plain
                    const uint32_t gd = G ? HB_DELTA : 0u;
#pragma unroll
                    for (int r = 1; r < CLV; r++)
                        st_cluster_b64(peer_hbA[r] + gd + boff * 4, pv);
                }
                __syncthreads();
                if (tid < CLV) {
                    fence_cluster();
                    mbar_arrive_remote(my_peer_mb + mboff + bcur * 8);
                }
            }
            if (lane < NO) {
                out[step_off + obase] = hval;
                if (t == SEQ) out[(size_t)SEQ * BATCH * HDIM + obase] = hval;
            }
        }
    }
}

// ---------------------------------------------------------------------------
extern "C" void kernel_launch(void* const* d_in, const int* in_sizes, int n_in,
                              void* d_out, int out_size)
{
    const float* x  = (const float*)d_in[0];
    const float* Wi = (const float*)d_in[1];
    const float* bi = (const float*)d_in[2];
    const float* Wh = (const float*)d_in[3];
    const float* bh = (const float*)d_in[4];
    float* out = (float*)d_out;

    const int XI_SMEM = (128 * 130 + 64 * 130) * 4;
    const int SMEM16  = ((HDIM / 16) * HDIM + 4 * GROWS * HDIM) * 4 + 32;  //  98336
    const int SMEM8   = ((HDIM / 8)  * HDIM + 4 * GROWS * HDIM) * 4 + 32;  // 163872

    cudaFuncSetAttribute(xi_kernel, cudaFuncAttributeMaxDynamicSharedMemorySize, XI_SMEM);
    cudaFuncSetAttribute(rnn_kernel<16>, cudaFuncAttributeNonPortableClusterSizeAllowed, 1);
    cudaFuncSetAttribute(rnn_kernel<16>, cudaFuncAttributeMaxDynamicSharedMemorySize, SMEM16);
    cudaFuncSetAttribute(rnn_kernel<8>,  cudaFuncAttributeMaxDynamicSharedMemorySize, SMEM8);

    xi_kernel<<<dim3(32768 / 64, HDIM / 128), 256, XI_SMEM>>>(x, Wi, bi, bh, out);

    // preferred: 8 clusters x 16 CTAs (non-portable cluster size)
    cudaLaunchConfig_t cfg = {};
    cfg.gridDim  = dim3(8 * 16, 1, 1);
    cfg.blockDim = dim3(RT, 1, 1);
    cfg.dynamicSmemBytes = SMEM16;
    cudaLaunchAttribute at[1];
    at[0].id = cudaLaunchAttributeClusterDimension;
    at[0].val.clusterDim = {16, 1, 1};
    cfg.attrs = at;
    cfg.numAttrs = 1;

    int nclust = 0;
    cudaError_t q = cudaOccupancyMaxActiveClusters(&nclust, rnn_kernel<16>, &cfg);
    (void)cudaGetLastError();   // clear any query error; decide host-side

    if (q == cudaSuccess && nclust >= 8) {
        cudaLaunchKernelEx(&cfg, rnn_kernel<16>, Wh, out);
    } else {
        // fallback: 8 clusters x 8 CTAs (portable; == validated R10 design)
        cudaLaunchConfig_t cfg8 = {};
        cfg8.gridDim  = dim3(8 * 8, 1, 1);
        cfg8.blockDim = dim3(RT, 1, 1);
        cfg8.dynamicSmemBytes = SMEM8;
        cudaLaunchAttribute at8[1];
        at8[0].id = cudaLaunchAttributeClusterDimension;
        at8[0].val.clusterDim = {8, 1, 1};
        cfg8.attrs = at8;
        cfg8.numAttrs = 1;
        cudaLaunchKernelEx(&cfg8, rnn_kernel<8>, Wh, out);
    }
}

// round 12
// speedup vs baseline: 1.2942x; 1.2942x over previous
#include <cuda_runtime.h>
#include <cstdint>
#include <cstddef>

#define SEQ    512
#define BATCH  64
#define INDIM  128
#define HDIM   512

#define CL     8            // CTAs per cluster (H split)
#define NCLUST 8            // clusters; each serves 8 batch rows (2 groups of 4)
#define GROWS  4            // rows per group
#define JC     (HDIM / CL)  // 64 j columns per CTA
#define NCW    8            // compute warps
#define RT     (NCW * 32 + 32)   // 288: 8 compute warps + 1 comm warp

typedef unsigned long long u64;

__device__ __forceinline__ u64 fma2(u64 a, u64 b, u64 c) {
    u64 d;
    asm("fma.rn.f32x2 %0, %1, %2, %3;" : "=l"(d) : "l"(a), "l"(b), "l"(c));
    return d;
}
__device__ __forceinline__ uint32_t smem_u32(const void* p) {
    uint32_t a;
    asm("{ .reg .u64 t; cvta.to.shared.u64 t, %1; cvt.u32.u64 %0, t; }" : "=r"(a) : "l"(p));
    return a;
}
__device__ __forceinline__ uint32_t mapa_u32(uint32_t a, uint32_t r) {
    uint32_t d;
    asm("mapa.shared::cluster.u32 %0, %1, %2;" : "=r"(d) : "r"(a), "r"(r));
    return d;
}
__device__ __forceinline__ void mbar_init(uint32_t a, uint32_t cnt) {
    asm volatile("mbarrier.init.shared.b64 [%0], %1;" :: "r"(a), "r"(cnt) : "memory");
}
__device__ __forceinline__ void mbar_wait_cluster(uint32_t a, uint32_t parity) {
    asm volatile(
        "{\n\t"
        ".reg .pred P;\n\t"
        "WL_%=:\n\t"
        "mbarrier.try_wait.parity.acquire.cluster.shared::cta.b64 P, [%0], %1, 0x989680;\n\t"
        "@P bra.uni WD_%=;\n\t"
        "bra.uni WL_%=;\n\t"
        "WD_%=:\n\t"
        "}"
        :: "r"(a), "r"(parity) : "memory");
}
__device__ __forceinline__ void mbar_arrive_remote(uint32_t a) {
    asm volatile("mbarrier.arrive.release.cluster.shared::cluster.b64 _, [%0];"
                 :: "r"(a) : "memory");
}
__device__ __forceinline__ void fence_cluster() {
    asm volatile("fence.acq_rel.cluster;" ::: "memory");
}
__device__ __forceinline__ void st_cluster_b64(uint32_t a, u64 v) {
    asm volatile("st.shared::cluster.b64 [%0], %1;" :: "r"(a), "l"(v) : "memory");
}
__device__ __forceinline__ void nbar_arrive(int id) {   // non-blocking
    asm volatile("bar.arrive %0, %1;" :: "r"(id), "r"(RT) : "memory");
}
__device__ __forceinline__ void nbar_sync(int id) {     // blocking (comm warp)
    asm volatile("bar.sync %0, %1;" :: "r"(id), "r"(RT) : "memory");
}
#define CLUSTER_SYNC() do { \
    asm volatile("barrier.cluster.arrive.aligned;" ::: "memory"); \
    asm volatile("barrier.cluster.wait.aligned;"   ::: "memory"); \
} while (0)

// ---------------------------------------------------------------------------
// xi kernel (validated R3-R11): out[s][b][h] = x.Wi + bi + bh
// ---------------------------------------------------------------------------
__global__ __launch_bounds__(256) void xi_kernel(
    const float* __restrict__ x, const float* __restrict__ Wi,
    const float* __restrict__ bi, const float* __restrict__ bh,
    float* __restrict__ out)
{
    extern __shared__ float sm[];
    float* ws = sm;               // [128][130]
    float* xs = sm + 128 * 130;   // [64][130]

    const int tid = threadIdx.x;
    const int sb0 = blockIdx.x * 64;
    const int h0  = blockIdx.y * 128;

    for (int i = tid; i < 128 * INDIM; i += 256) {
        int r = i >> 7, k = i & 127;
        ws[r * 130 + k] = Wi[(h0 + r) * INDIM + k];
    }
    for (int i = tid; i < 64 * INDIM; i += 256) {
        int r = i >> 7, k = i & 127;
        xs[r * 130 + k] = x[(size_t)(sb0 + r) * INDIM + k];
    }
    __syncthreads();

    const int w  = tid >> 5;
    const int tx = tid & 31;

    u64 acc2[8][4];
#pragma unroll
    for (int i = 0; i < 8; i++)
#pragma unroll
        for (int j = 0; j < 4; j++) acc2[i][j] = 0ull;

    const u64* xb2 = (const u64*)xs + (w * 8) * 65;
    const u64* wb2 = (const u64*)ws;

#pragma unroll 4
    for (int kp = 0; kp < 64; kp++) {
        u64 xv[8], wv[4];
#pragma unroll
        for (int i = 0; i < 8; i++) xv[i] = xb2[i * 65 + kp];
#pragma unroll
        for (int j = 0; j < 4; j++) wv[j] = wb2[(j * 32 + tx) * 65 + kp];
#pragma unroll
        for (int i = 0; i < 8; i++)
#pragma unroll
            for (int j = 0; j < 4; j++) acc2[i][j] = fma2(xv[i], wv[j], acc2[i][j]);
    }

#pragma unroll
    for (int j = 0; j < 4; j++) {
        int h = h0 + j * 32 + tx;
        float b = bi[h] + bh[h];
#pragma unroll
        for (int i = 0; i < 8; i++) {
            float2 a = *reinterpret_cast<float2*>(&acc2[i][j]);
            out[(size_t)(sb0 + w * 8 + i) * HDIM + h] = a.x + a.y + b;
        }
    }
}

// ---------------------------------------------------------------------------
// Recurrence: 8 clusters x 8 CTAs, A/B interleave, COMM-WARP SPECIALIZED.
// Warps 0-7 compute; warp 8 is the comm warp. Compute path per half-step:
// mbar fast-path wait -> LDS.128/fma2 -> butterfly -> tanh -> weak DSMEM
// push -> bar.arrive (non-blocking) -> next group. Comm warp: bar.sync ->
// lanes 0-7 fence.acq_rel.cluster + one remote release-arrive. The fence
// drain (the R10/R11 critical-path cost) is now off the compute timeline.
// Named barrier ids: A uses {1,2} (ping-pong), B uses {3,4}.
// ---------------------------------------------------------------------------
__global__ __launch_bounds__(RT, 1) __cluster_dims__(CL, 1, 1)
void rnn_kernel(const float* __restrict__ Wh, float* __restrict__ out)
{
    extern __shared__ float sm[];
    float* sWh = sm;                          // [64][512]       128 KB
    float* hbA = sm + JC * HDIM;              // [2][4][512]      16 KB
    float* hbB = hbA + 2 * GROWS * HDIM;      // [2][4][512]      16 KB
    u64*   mbar = (u64*)(hbB + 2 * GROWS * HDIM);  // A0,A1,B0,B1

    const int tid = threadIdx.x;
    const int w   = tid >> 5;           // 0..7 compute, 8 comm
    const int lane = tid & 31;
    uint32_t rank;
    asm("mov.u32 %0, %%cluster_ctarank;" : "=r"(rank));
    const int gbase = (blockIdx.x / CL) * 8;

    const uint32_t mb_base = smem_u32(mbar);
    if (tid == 0) {
#pragma unroll
        for (int i = 0; i < 4; i++) mbar_init(mb_base + i * 8, CL);
    }
    {   // load Wh rows [rank*JC, +JC) once (all 9 warps help)
        const float4* src = (const float4*)(Wh + (size_t)rank * JC * HDIM);
        float4* dst = (float4*)sWh;
        for (int i = tid; i < JC * HDIM / 4; i += RT) dst[i] = src[i];
    }
    __syncthreads();
    CLUSTER_SYNC();   // peers' mbarriers live before any arrive

    // ======================= comm warp =======================
    if (w == NCW) {
        const uint32_t my_peer_mb = (lane < CL)
            ? mapa_u32(mb_base, (rank + lane) & (CL - 1)) : 0u;
        for (int t = 1; t < SEQ; t++) {
            const int bcur = t & 1;
            // group A of step t
            nbar_sync(1 + bcur);               // ids 1,2
            if (lane < CL) {
                fence_cluster();               // drain CTA's DSMEM stores (A)
                mbar_arrive_remote(my_peer_mb + bcur * 8);
            }
            // group B of step t
            nbar_sync(3 + bcur);               // ids 3,4
            if (lane < CL) {
                fence_cluster();
                mbar_arrive_remote(my_peer_mb + 16 + bcur * 8);
            }
        }
        return;
    }

    // ======================= compute warps =======================
    const int b    = lane >> 3;         // output row in group (after butterfly)
    const int ojl  = rank * JC + w * 8 + (lane & 7);   // global j index
    const int obA  = gbase + b;
    const int obB  = gbase + 4 + b;

    const ulonglong2* wv2 = (const ulonglong2*)sWh + (w * 8) * (HDIM / 4) + lane;

    const uint32_t hbA_base = smem_u32(hbA);
    uint32_t peer_hbA[CL];
#pragma unroll
    for (int r = 0; r < CL; r++)
        peer_hbA[r] = mapa_u32(hbA_base, (rank + r) & (CL - 1));
    const uint32_t HB_DELTA = 2 * GROWS * HDIM * 4;   // hbB - hbA bytes

    int phA[2] = {0, 0}, phB[2] = {0, 0};

    const size_t obaseA = (size_t)obA * HDIM + ojl;
    const size_t obaseB = (size_t)obB * HDIM + ojl;
    float xiA = __ldg(out + obaseA);
    float xiB = __ldg(out + obaseB);

    for (int t = 1; t <= SEQ; t++) {
        const int bcur  = t & 1;
        const int bprev = 1 - bcur;
        const size_t step_off = (size_t)(t - 1) * (BATCH * HDIM);

#pragma unroll
        for (int G = 0; G < 2; G++) {
            float* hbG = G ? hbB : hbA;
            const uint32_t gd = G ? HB_DELTA : 0u;
            int* phG = G ? phB : phA;
            const float xiv = G ? xiB : xiA;
            const size_t obase = G ? obaseB : obaseA;

            float sum = 0.f;
            if (t > 1) {
                mbar_wait_cluster(mb_base + G * 16 + bprev * 8, phG[bprev]);
                phG[bprev] ^= 1;
                const ulonglong2* hp =
                    (const ulonglong2*)(hbG + bprev * GROWS * HDIM) + lane;

                u64 acc[4][8];
#pragma unroll
                for (int i = 0; i < 4; i++)
#pragma unroll
                    for (int j = 0; j < 8; j++) acc[i][j] = 0ull;
#pragma unroll
                for (int d = 0; d < 4; d++) {    // k = d*128 + lane*4
                    ulonglong2 hv[4], wv[8];
#pragma unroll
                    for (int i = 0; i < 4; i++) hv[i] = hp[i * (HDIM / 4) + d * 32];
#pragma unroll
                    for (int j = 0; j < 8; j++) wv[j] = wv2[j * (HDIM / 4) + d * 32];
#pragma unroll
                    for (int i = 0; i < 4; i++)
#pragma unroll
                        for (int j = 0; j < 8; j++) {
                            acc[i][j] = fma2(hv[i].x, wv[j].x, acc[i][j]);
                            acc[i][j] = fma2(hv[i].y, wv[j].y, acc[i][j]);
                        }
                }
                float v[32];
#pragma unroll
                for (int i = 0; i < 4; i++)
#pragma unroll
                    for (int j = 0; j < 8; j++) {
                        float2 a = *reinterpret_cast<float2*>(&acc[i][j]);
                        v[i * 8 + j] = a.x + a.y;
                    }
#pragma unroll
                for (int m = 0; m < 5; m++) {
                    const int mb2 = (lane >> m) & 1;
#pragma unroll
                    for (int j2 = 0; j2 < (16 >> m); j2++) {
                        float send = v[2 * j2 + 1 - mb2];
                        float recv = __shfl_xor_sync(0xffffffffu, send, 1 << m);
                        v[j2] = v[2 * j2 + mb2] + recv;
                    }
                }
                sum = v[0];
            }

            const float hval = tanhf(sum + xiv);
            if (t < SEQ) {
                float nv = __ldg(out + step_off + BATCH * HDIM + obase);
                if (G) xiB = nv; else xiA = nv;
            }

            if (t < SEQ) {
                float nxt = __shfl_down_sync(0xffffffffu, hval, 1);
                if (!(lane & 1)) {   // even lanes push packed (j, j+1)
                    float2 p2 = make_float2(hval, nxt);
                    u64 pv = *reinterpret_cast<u64*>(&p2);
                    const uint32_t boff = bcur * GROWS * HDIM + b * HDIM + ojl;
                    *reinterpret_cast<u64*>(hbG + boff) = pv;   // self, plain
#pragma unroll
                    for (int r = 1; r < CL; r++)
                        st_cluster_b64(peer_hbA[r] + gd + boff * 4, pv);
                }
                nbar_arrive(1 + G * 2 + bcur);   // non-blocking handoff to comm
            }

            out[step_off + obase] = hval;
            if (t == SEQ) out[(size_t)SEQ * BATCH * HDIM + obase] = hval;
        }
    }
}

// ---------------------------------------------------------------------------
extern "C" void kernel_launch(void* const* d_in, const int* in_sizes, int n_in,
                              void* d_out, int out_size)
{
    const float* x  = (const float*)d_in[0];
    const float* Wi = (const float*)d_in[1];
    const float* bi = (const float*)d_in[2];
    const float* Wh = (const float*)d_in[3];
    const float* bh = (const float*)d_in[4];
    float* out = (float*)d_out;

    const int XI_SMEM  = (128 * 130 + 64 * 130) * 4;                 // 99840 B
    const int RNN_SMEM = (JC * HDIM + 4 * GROWS * HDIM) * 4 + 32;    // 163872 B

    cudaFuncSetAttribute(xi_kernel,  cudaFuncAttributeMaxDynamicSharedMemorySize, XI_SMEM);
    cudaFuncSetAttribute(rnn_kernel, cudaFuncAttributeMaxDynamicSharedMemorySize, RNN_SMEM);

    xi_kernel<<<dim3(32768 / 64, HDIM / 128), 256, XI_SMEM>>>(x, Wi, bi, bh, out);
    rnn_kernel<<<NCLUST * CL, RT, RNN_SMEM>>>(Wh, out);
}